// round 2
// baseline (speedup 1.0000x reference)
#include <cuda_runtime.h>
#include <math.h>

#define N_ROI 2000
#define N_CLS 21
#define N_GT  20
#define N_PIX 1900
#define N_CH  512
#define OUT_DETS (20 * N_ROI * 5)   // 200000
#define TPB 512

// Scratch for feature-loss reduction (no allocations allowed)
__device__ float g_part[8][3][N_PIX];
__device__ float g_mean[3][N_PIX];

__global__ void zero_kernel(float* out, int n) {
    int i = blockIdx.x * blockDim.x + threadIdx.x;
    if (i < n) out[i] = 0.0f;
}

// One block per class (cls = blockIdx.x + 1, skipping background).
// Phase 1: compact boxes with score > 0.5 into shared (csc/cid).
// Phase 2: stable-sort ranks by brute-force counting (desc score, tie -> lower idx).
// Phase 3: decode + scatter boxes into sorted order.
// Phase 4: greedy NMS via suppress bitmask; kept boxes checked vs GT and written out.
__global__ void __launch_bounds__(TPB) nms_kernel(
    const float* __restrict__ rois, const float* __restrict__ cls_prob,
    const float* __restrict__ bbox_pred, const float* __restrict__ im_info,
    const float* __restrict__ gt_boxes, const int* __restrict__ num_boxes,
    float* __restrict__ out)
{
    extern __shared__ unsigned char smem_raw[];
    float4*       sbox = (float4*)smem_raw;          // [N_ROI] sorted boxes
    float*        ss   = (float*)(sbox + N_ROI);     // [N_ROI] sorted scores
    float*        csc  = ss + N_ROI;                 // [N_ROI] compact scores
    short*        cid  = (short*)(csc + N_ROI);      // [N_ROI] compact orig idx
    float4*       sgt  = (float4*)(cid + N_ROI);     // [N_GT]
    unsigned int* sup  = (unsigned int*)(sgt + N_GT);// [64] suppression bitmask
    __shared__ int sKv, sPos, sNum, s_i;

    const int tid = threadIdx.x;
    const int cls = blockIdx.x + 1;

    if (tid == 0) sKv = 0;
    __syncthreads();

    // ---- Phase 1: compaction ----
    float mysc[4];
    int   myid[4];
    int   mycnt = 0;
    for (int i = tid; i < N_ROI; i += TPB) {
        float s = cls_prob[i * N_CLS + cls];
        if (s > 0.5f) {
            int slot = atomicAdd(&sKv, 1);
            csc[slot] = s;
            cid[slot] = (short)i;
            mysc[mycnt] = s; myid[mycnt] = i; mycnt++;
        }
    }
    __syncthreads();
    const int Kv = sKv;

    // ---- Phase 2: rank = #elements strictly before me in stable sort ----
    int myrank[4] = {0, 0, 0, 0};
    for (int k = 0; k < Kv; k++) {
        float sk = csc[k];
        int   ik = (int)cid[k];
        #pragma unroll
        for (int j = 0; j < 4; j++) {
            if (j < mycnt)
                myrank[j] += (sk > mysc[j]) || (sk == mysc[j] && ik < myid[j]);
        }
    }

    // ---- Phase 3: decode + scatter into sorted order ----
    const float Hm1 = im_info[0] - 1.0f;
    const float Wm1 = im_info[1] - 1.0f;
    for (int j = 0; j < mycnt; j++) {
        int i = myid[j];
        float x1 = rois[i * 5 + 1], y1 = rois[i * 5 + 2];
        float x2 = rois[i * 5 + 3], y2 = rois[i * 5 + 4];
        float w = x2 - x1 + 1.0f, h = y2 - y1 + 1.0f;
        float cx = x1 + 0.5f * w, cy = y1 + 0.5f * h;
        const float* d = bbox_pred + ((size_t)i * N_CLS + (size_t)cls) * 4;
        float dx = d[0] * 0.1f, dy = d[1] * 0.1f;
        float dw = d[2] * 0.2f, dh = d[3] * 0.2f;
        float pcx = dx * w + cx, pcy = dy * h + cy;
        float pw = expf(dw) * w, ph = expf(dh) * h;
        float px1 = pcx - 0.5f * pw, py1 = pcy - 0.5f * ph;
        float px2 = pcx + 0.5f * pw, py2 = pcy + 0.5f * ph;
        px1 = fminf(fmaxf(px1, 0.0f), Wm1);
        py1 = fminf(fmaxf(py1, 0.0f), Hm1);
        px2 = fminf(fmaxf(px2, 0.0f), Wm1);
        py2 = fminf(fmaxf(py2, 0.0f), Hm1);
        int r = myrank[j];
        sbox[r] = make_float4(px1, py1, px2, py2);
        ss[r]   = mysc[j];
    }
    if (tid == 0) {
        sPos = 0;
        int nb = num_boxes[0];
        sNum = nb < 0 ? 0 : (nb > N_GT ? N_GT : nb);
    }
    for (int g = tid; g < N_GT; g += TPB)
        sgt[g] = make_float4(gt_boxes[g * 5 + 0], gt_boxes[g * 5 + 1],
                             gt_boxes[g * 5 + 2], gt_boxes[g * 5 + 3]);
    for (int wv = tid; wv < 64; wv += TPB) sup[wv] = 0u;
    __syncthreads();

    // ---- Phase 4: greedy NMS ----
    float* outc = out + (size_t)(cls - 1) * N_ROI * 5;
    const int numgt = sNum;
    while (true) {
        if (tid == 0) {
            int i = sPos;
            while (i < Kv && ((sup[i >> 5] >> (i & 31)) & 1u)) i++;
            s_i = (i < Kv) ? i : -1;
            sPos = i + 1;
        }
        __syncthreads();
        const int i = s_i;
        if (i < 0) break;
        const float4 b = sbox[i];
        const float areaA = (b.z - b.x) * (b.w - b.y);
        // suppress later boxes overlapping the kept box
        for (int k = i + 1 + tid; k < Kv; k += TPB) {
            float4 c = sbox[k];
            float areaB = (c.z - c.x) * (c.w - c.y);
            float lx = fmaxf(b.x, c.x), ly = fmaxf(b.y, c.y);
            float rx = fminf(b.z, c.z), ry = fminf(b.w, c.w);
            float ww = fmaxf(rx - lx, 0.0f), hh = fmaxf(ry - ly, 0.0f);
            float inter = ww * hh;
            float iou = inter / (areaA + areaB - inter + 1e-6f);
            if (iou > 0.3f) atomicOr(&sup[k >> 5], 1u << (k & 31));
        }
        // GT dedup + output for the kept box (warp 0)
        if (tid < 32) {
            bool hit = false;
            if (tid < numgt) {
                float4 c = sgt[tid];
                float areaB = (c.z - c.x) * (c.w - c.y);
                float lx = fmaxf(b.x, c.x), ly = fmaxf(b.y, c.y);
                float rx = fminf(b.z, c.z), ry = fminf(b.w, c.w);
                float ww = fmaxf(rx - lx, 0.0f), hh = fmaxf(ry - ly, 0.0f);
                float inter = ww * hh;
                float iou = inter / (areaA + areaB - inter + 1e-6f);
                hit = iou > 0.3f;
            }
            unsigned any = __ballot_sync(0xffffffffu, hit);
            if (tid == 0 && any == 0u) {
                outc[(size_t)i * 5 + 0] = b.x;
                outc[(size_t)i * 5 + 1] = b.y;
                outc[(size_t)i * 5 + 2] = b.z;
                outc[(size_t)i * 5 + 3] = b.w;
                outc[(size_t)i * 5 + 4] = ss[i];
            }
        }
        __syncthreads();
    }
}

// Per-pixel channel partial sums: grid (8 pixel chunks, 8 channel groups of 64)
__global__ void chan_part_kernel(const float* __restrict__ f,
                                 const float* __restrict__ fo,
                                 const float* __restrict__ fr) {
    int p = blockIdx.x * 256 + threadIdx.x;
    int g = blockIdx.y;
    if (p >= N_PIX) return;
    const float* pf = f  + (size_t)g * 64 * N_PIX + p;
    const float* po = fo + (size_t)g * 64 * N_PIX + p;
    const float* pr = fr + (size_t)g * 64 * N_PIX + p;
    float s0 = 0.f, s1 = 0.f, s2 = 0.f;
    #pragma unroll 8
    for (int c = 0; c < 64; c++) {
        s0 += pf[(size_t)c * N_PIX];
        s1 += po[(size_t)c * N_PIX];
        s2 += pr[(size_t)c * N_PIX];
    }
    g_part[g][0][p] = s0;
    g_part[g][1][p] = s1;
    g_part[g][2][p] = s2;
}

__global__ void chan_comb_kernel() {
    int p = blockIdx.x * 256 + threadIdx.x;
    if (p >= N_PIX) return;
    #pragma unroll
    for (int t = 0; t < 3; t++) {
        float s = 0.f;
        #pragma unroll
        for (int g = 0; g < 8; g++) s += g_part[g][t][p];
        g_mean[t][p] = s * (1.0f / 512.0f);
    }
}

__global__ void finalize_kernel(float* __restrict__ out) {
    __shared__ float red[256];
    int tid = threadIdx.x;
    float a0 = 0.f, a1 = 0.f, a2 = 0.f, a3 = 0.f, a4 = 0.f;
    for (int p = tid; p < N_PIX; p += 256) {
        float mf = g_mean[0][p], mo = g_mean[1][p], mr = g_mean[2][p];
        a0 += mf * mf;
        a1 += mo * mo;
        float d = mf - mo; a2 += d * d;
        a3 += mr * mr;
        float s = mo + mr; a4 += s * s;
    }
    float acc[5] = {a0, a1, a2, a3, a4};
    float tot[5];
    for (int t = 0; t < 5; t++) {
        red[tid] = acc[t];
        __syncthreads();
        for (int off = 128; off > 0; off >>= 1) {
            if (tid < off) red[tid] += red[tid + off];
            __syncthreads();
        }
        tot[t] = red[0];
        __syncthreads();
    }
    if (tid == 0) {
        float n_f  = sqrtf(tot[0]);
        float n_fo = sqrtf(tot[1]);
        float distil   = fabsf(n_f - n_fo);
        float res_loss = fabsf(sqrtf(tot[2]) - sqrtf(tot[3]));
        float res_inc  = fabsf(sqrtf(tot[4]) - n_f);
        out[OUT_DETS + 0] = distil;
        out[OUT_DETS + 1] = res_inc + res_loss;
    }
}

extern "C" void kernel_launch(void* const* d_in, const int* in_sizes, int n_in,
                              void* d_out, int out_size) {
    const float* rois      = (const float*)d_in[0];
    const float* cls_prob  = (const float*)d_in[1];
    const float* bbox_pred = (const float*)d_in[2];
    const float* im_info   = (const float*)d_in[3];
    const float* gt_boxes  = (const float*)d_in[4];
    const int*   num_boxes = (const int*)d_in[5];
    const float* feat      = (const float*)d_in[6];
    const float* feat_org  = (const float*)d_in[7];
    const float* feat_res  = (const float*)d_in[8];
    float* out = (float*)d_out;

    const int smem_nms = (int)(sizeof(float4) * N_ROI      // sbox   32000
                             + sizeof(float) * N_ROI * 2   // ss+csc 16000
                             + sizeof(short) * N_ROI       // cid     4000
                             + sizeof(float4) * N_GT       // sgt      320
                             + sizeof(unsigned int) * 64); //          256
    cudaFuncSetAttribute(nms_kernel, cudaFuncAttributeMaxDynamicSharedMemorySize,
                         smem_nms);

    int total_out = OUT_DETS + 2;
    zero_kernel<<<(total_out + 255) / 256, 256>>>(out, total_out);
    nms_kernel<<<20, TPB, smem_nms>>>(rois, cls_prob, bbox_pred, im_info,
                                      gt_boxes, num_boxes, out);
    dim3 gpart((N_PIX + 255) / 256, 8);
    chan_part_kernel<<<gpart, 256>>>(feat, feat_org, feat_res);
    chan_comb_kernel<<<(N_PIX + 255) / 256, 256>>>();
    finalize_kernel<<<1, 256>>>(out);
}